// round 4
// baseline (speedup 1.0000x reference)
#include <cuda_runtime.h>
#include <math_constants.h>

// Banded DTW (Sakoe-Chiba w=1) as a tropical (min,+) 3x3 matrix product.
// Per-row band update is min-plus linear in (p0,p1,p2):
//   n0 = a0 + min(p0,p1)               (forced INF when k==0)
//   n1 = a1 + min(n0, p1, p2)
//   n2 = a2 + min(n1, p2)              (forced INF when k==n-1)
// => total map = M_{n-1} (*) ... (*) M_0, associative (NOT commutative)
// => parallel tree reduce with strictly order-preserving pairwise combines.
// Answer = (P_total applied to (INF,0,INF))[1] = P_total[1][1].

#define NBLK 128
#define NTHR 256

__device__ float g_block_mats[NBLK * 9];

struct Mat {
    float m[3][3];
};

// total = B after A (A earlier): C[r][c] = min_k B[r][k] + A[k][c]
__device__ __forceinline__ Mat mp_mul(const Mat& B, const Mat& A) {
    Mat C;
#pragma unroll
    for (int r = 0; r < 3; r++) {
#pragma unroll
        for (int c = 0; c < 3; c++) {
            float v = B.m[r][0] + A.m[0][c];
            v = fminf(v, B.m[r][1] + A.m[1][c]);
            v = fminf(v, B.m[r][2] + A.m[2][c]);
            C.m[r][c] = v;
        }
    }
    return C;
}

__device__ __forceinline__ void store_mat(float sm[9][NTHR > NBLK ? NTHR : NBLK],
                                          int slot, const Mat& P) {
#pragma unroll
    for (int r = 0; r < 3; r++)
#pragma unroll
        for (int c = 0; c < 3; c++)
            sm[r * 3 + c][slot] = P.m[r][c];
}

__device__ __forceinline__ Mat load_mat(const float sm[9][NTHR > NBLK ? NTHR : NBLK],
                                        int slot) {
    Mat P;
#pragma unroll
    for (int r = 0; r < 3; r++)
#pragma unroll
        for (int c = 0; c < 3; c++)
            P.m[r][c] = sm[r * 3 + c][slot];
    return P;
}

__global__ void dtw_stage1(const float* __restrict__ outp,
                           const float* __restrict__ tgt,
                           int n, int chunk) {
    const float INF = CUDART_INF_F;
    const int t = threadIdx.x;
    const int g = blockIdx.x * blockDim.x + t;
    const long long base = (long long)g * chunk;

    // identity in (min,+): 0 on diagonal, INF elsewhere
    Mat P;
#pragma unroll
    for (int r = 0; r < 3; r++)
#pragma unroll
        for (int c = 0; c < 3; c++)
            P.m[r][c] = (r == c) ? 0.0f : INF;

    for (int j = 0; j < chunk; j++) {
        long long k = base + j;      // 0-indexed step; DP row i = k+1
        if (k >= n) break;
        float o  = outp[k];
        float tm = tgt[k];
        float tl = tgt[(k >= 1) ? (k - 1) : 0];          // masked when k==0
        float th = tgt[(k + 1 < n) ? (k + 1) : (n - 1)]; // masked when k==n-1
        float a0 = fabsf(o - tl);
        float a1 = fabsf(o - tm);
        float a2 = fabsf(o - th);
        bool mask0 = (k == 0);
        bool mask2 = (k == (long long)n - 1);
#pragma unroll
        for (int c = 0; c < 3; c++) {
            float p0 = P.m[0][c], p1 = P.m[1][c], p2 = P.m[2][c];
            float n0 = a0 + fminf(p0, p1);
            n0 = mask0 ? INF : n0;
            float n1 = a1 + fminf(n0, fminf(p1, p2));
            float n2 = a2 + fminf(n1, p2);
            n2 = mask2 ? INF : n2;
            P.m[0][c] = n0;
            P.m[1][c] = n1;
            P.m[2][c] = n2;
        }
    }

    // ORDER-PRESERVING pairwise tree reduce: slot t <- c[2t+1] (*) c[2t]
    __shared__ float sm[9][NTHR];
    store_mat(sm, t, P);
    __syncthreads();

    for (int cnt = NTHR; cnt > 1; cnt >>= 1) {
        int half = cnt >> 1;
        Mat A, B;
        bool active = (t < half);
        if (active) {
            A = load_mat(sm, 2 * t);       // earlier
            B = load_mat(sm, 2 * t + 1);   // later
        }
        __syncthreads();
        if (active) {
            P = mp_mul(B, A);
            store_mat(sm, t, P);
        }
        __syncthreads();
    }

    if (t == 0) {
#pragma unroll
        for (int r = 0; r < 3; r++)
#pragma unroll
            for (int c = 0; c < 3; c++)
                g_block_mats[blockIdx.x * 9 + r * 3 + c] = P.m[r][c];
    }
}

__global__ void dtw_stage2(float* __restrict__ d_out) {
    const int t = threadIdx.x;
    __shared__ float sm[9][NTHR > NBLK ? NTHR : NBLK];

    Mat P;
#pragma unroll
    for (int r = 0; r < 3; r++)
#pragma unroll
        for (int c = 0; c < 3; c++)
            P.m[r][c] = g_block_mats[t * 9 + r * 3 + c];
    store_mat(sm, t, P);
    __syncthreads();

    for (int cnt = NBLK; cnt > 1; cnt >>= 1) {
        int half = cnt >> 1;
        Mat A, B;
        bool active = (t < half);
        if (active) {
            A = load_mat(sm, 2 * t);       // earlier
            B = load_mat(sm, 2 * t + 1);   // later
        }
        __syncthreads();
        if (active) {
            P = mp_mul(B, A);
            store_mat(sm, t, P);
        }
        __syncthreads();
    }

    if (t == 0) {
        // state init = (INF, 0, INF) -> answer = P[1][1]
        d_out[0] = P.m[1][1];
    }
}

extern "C" void kernel_launch(void* const* d_in, const int* in_sizes, int n_in,
                              void* d_out, int out_size) {
    const float* outp = (const float*)d_in[0];
    const float* tgt  = (const float*)d_in[1];
    int n = in_sizes[0];

    const long long tot = (long long)NBLK * NTHR;
    int chunk = (int)((n + tot - 1) / tot);
    if (chunk < 1) chunk = 1;

    dtw_stage1<<<NBLK, NTHR>>>(outp, tgt, n, chunk);
    dtw_stage2<<<1, NBLK>>>((float*)d_out);
}

// round 5
// speedup vs baseline: 1.2000x; 1.2000x over previous
#include <cuda_runtime.h>
#include <math_constants.h>

// Banded DTW (Sakoe-Chiba w=1) as a tropical (min,+) 3x3 matrix product,
// fully fused into ONE kernel launch:
//   - each thread folds `chunk` consecutive DP steps into a 3x3 min-plus matrix
//   - order-preserving warp-shuffle tree reduce (later (*) earlier) within warp
//   - cross-warp reduce via tiny shared round
//   - last-block-to-finish (fence + atomic counter) performs the grid-level
//     reduce of the 128 block matrices and writes d[n,n] = P_total[1][1].
// Counter is reset by the last block -> deterministic across graph replays.

#define NBLK 128
#define NTHR 256
#define NWARP (NTHR / 32)

__device__ float g_block_mats[NBLK * 9];
__device__ unsigned int g_counter = 0;

struct Mat {
    float m[9];  // row-major [r*3+c]
};

// total = B after A (A earlier): C[r][c] = min_k B[r][k] + A[k][c]
__device__ __forceinline__ Mat mp_mul(const Mat& B, const Mat& A) {
    Mat C;
#pragma unroll
    for (int r = 0; r < 3; r++) {
#pragma unroll
        for (int c = 0; c < 3; c++) {
            float v = B.m[r * 3 + 0] + A.m[0 * 3 + c];
            v = fminf(v, B.m[r * 3 + 1] + A.m[1 * 3 + c]);
            v = fminf(v, B.m[r * 3 + 2] + A.m[2 * 3 + c]);
            C.m[r * 3 + c] = v;
        }
    }
    return C;
}

__device__ __forceinline__ Mat mat_identity() {
    Mat P;
#pragma unroll
    for (int i = 0; i < 9; i++) P.m[i] = CUDART_INF_F;
    P.m[0] = 0.0f; P.m[4] = 0.0f; P.m[8] = 0.0f;
    return P;
}

__device__ __forceinline__ Mat shfl_down_mat(const Mat& P, int s) {
    Mat R;
#pragma unroll
    for (int i = 0; i < 9; i++)
        R.m[i] = __shfl_down_sync(0xFFFFFFFFu, P.m[i], s);
    return R;
}

// Order-preserving warp reduce: after level s, lane t holds the product of the
// contiguous range [t, t+2s) (combined as later (*) earlier). Lane 0 ends with
// the whole warp's range. Lanes past the edge hold garbage that is never
// consumed by lane 0's dependency chain (or neutral identities when padded).
template <int WIDTH>
__device__ __forceinline__ Mat warp_reduce_ordered(Mat P) {
#pragma unroll
    for (int s = 1; s < WIDTH; s <<= 1) {
        Mat other = shfl_down_mat(P, s);  // later range [t+s, t+2s)
        P = mp_mul(other, P);
    }
    return P;
}

__global__ void dtw_fused(const float* __restrict__ outp,
                          const float* __restrict__ tgt,
                          float* __restrict__ d_out,
                          int n, int chunk) {
    const float INF = CUDART_INF_F;
    const int t = threadIdx.x;
    const int lane = t & 31;
    const int warp = t >> 5;
    const int g = blockIdx.x * NTHR + t;
    const long long base = (long long)g * chunk;

    // ---- per-thread sequential fold of `chunk` elementary step matrices ----
    Mat P = mat_identity();
    for (int j = 0; j < chunk; j++) {
        long long k = base + j;          // 0-indexed step; DP row i = k+1
        if (k >= n) break;
        float o  = outp[k];
        float tm = tgt[k];
        float tl = tgt[(k >= 1) ? (k - 1) : 0];          // masked when k==0
        float th = tgt[(k + 1 < n) ? (k + 1) : (n - 1)]; // masked when k==n-1
        float a0 = fabsf(o - tl);
        float a1 = fabsf(o - tm);
        float a2 = fabsf(o - th);
        bool mask0 = (k == 0);
        bool mask2 = (k == (long long)n - 1);
#pragma unroll
        for (int c = 0; c < 3; c++) {
            float p0 = P.m[0 * 3 + c], p1 = P.m[1 * 3 + c], p2 = P.m[2 * 3 + c];
            float n0 = a0 + fminf(p0, p1);
            n0 = mask0 ? INF : n0;
            float n1 = a1 + fminf(n0, fminf(p1, p2));
            float n2 = a2 + fminf(n1, p2);
            n2 = mask2 ? INF : n2;
            P.m[0 * 3 + c] = n0;
            P.m[1 * 3 + c] = n1;
            P.m[2 * 3 + c] = n2;
        }
    }

    // ---- in-warp ordered reduce: lane 0 of each warp holds its warp range ----
    P = warp_reduce_ordered<32>(P);

    // ---- cross-warp: NWARP partials through shared, warp 0 finishes ----
    __shared__ float s_warp[NWARP * 9];
    __shared__ bool s_islast;
    if (lane == 0) {
#pragma unroll
        for (int i = 0; i < 9; i++) s_warp[warp * 9 + i] = P.m[i];
    }
    __syncthreads();

    if (warp == 0) {
        Mat W = mat_identity();
        if (lane < NWARP) {
#pragma unroll
            for (int i = 0; i < 9; i++) W.m[i] = s_warp[lane * 9 + i];
        }
        W = warp_reduce_ordered<NWARP>(W);
        if (lane == 0) {
#pragma unroll
            for (int i = 0; i < 9; i++)
                g_block_mats[blockIdx.x * 9 + i] = W.m[i];
            __threadfence();
            unsigned int old = atomicAdd(&g_counter, 1u);
            s_islast = (old == (unsigned int)(gridDim.x - 1));
        }
    }
    __syncthreads();

    // ---- last block to arrive: grid-level reduce of NBLK matrices ----
    if (s_islast) {
        Mat F = mat_identity();
        if (t < NBLK) {
#pragma unroll
            for (int i = 0; i < 9; i++) F.m[i] = g_block_mats[t * 9 + i];
        }
        // warps 0..3 each reduce 32 contiguous block-matrices
        F = warp_reduce_ordered<32>(F);

        __shared__ float s_final[(NBLK / 32) * 9];
        if (lane == 0 && t < NBLK) {
#pragma unroll
            for (int i = 0; i < 9; i++) s_final[warp * 9 + i] = F.m[i];
        }
        __syncthreads();

        if (warp == 0) {
            Mat G = mat_identity();
            if (lane < NBLK / 32) {
#pragma unroll
                for (int i = 0; i < 9; i++) G.m[i] = s_final[lane * 9 + i];
            }
            G = warp_reduce_ordered<NBLK / 32>(G);
            if (lane == 0) {
                // initial state (INF, 0, INF) -> answer = P_total[1][1]
                d_out[0] = G.m[1 * 3 + 1];
                g_counter = 0u;  // reset for next (graph-replayed) call
            }
        }
    }
}

extern "C" void kernel_launch(void* const* d_in, const int* in_sizes, int n_in,
                              void* d_out, int out_size) {
    const float* outp = (const float*)d_in[0];
    const float* tgt  = (const float*)d_in[1];
    int n = in_sizes[0];

    const long long tot = (long long)NBLK * NTHR;
    int chunk = (int)((n + tot - 1) / tot);
    if (chunk < 1) chunk = 1;

    dtw_fused<<<NBLK, NTHR>>>(outp, tgt, (float*)d_out, n, chunk);
}